// round 14
// baseline (speedup 1.0000x reference)
#include <cuda_runtime.h>
#include <cuda_bf16.h>
#include <cstdint>

// GraphSage: out = relu( [self | mean(neigh)] @ W ),  B=50000, D=128, H=128, K=256.
// bf16x3 emulated fp32 on HMMA (mma.sync m16n8k16), compute_103-safe.
//
// Round-12: producer/consumer warp specialization. 256-thread persistent CTAs:
// warps 4-7 gather tile t into A-buffer s&1 while warps 0-3 run the MMA +
// epilogue for tile t-1 from buffer (s-1)&1; one __syncthreads per step.
// Gather (latency-bound) and MMA (issue-bound) now overlap deterministically.

#define NTHREADS 256
#define TILE_M   32
#define H_DIM    128
#define A_STRIDE 264            // elements; 528B rows = 33 chunks, ldmatrix conflict-free

// per-buffer block: AHI 16896 + ALO 16896 + IDX 1536 = 35328
#define BUF_BYTES 35328
#define SM_ALO    16896
#define SM_IDX    33792
#define SM_TOTAL  (2 * BUF_BYTES)   // 70656 (dynamic)

// W fragments: [kstep 0..15][colblk 0..15][lane 0..31] -> uint4{b0hi,b1hi,b0lo,b1lo}
__device__ uint4 g_wfrag[16 * 16 * 32];

__device__ __forceinline__ uint32_t s2u(const void* p) {
    uint32_t a;
    asm("{ .reg .u64 t; cvta.to.shared.u64 t, %1; cvt.u32.u64 %0, t; }" : "=r"(a) : "l"(p));
    return a;
}
__device__ __forceinline__ void ldsm_x4(uint32_t* r, uint32_t addr) {
    asm volatile("ldmatrix.sync.aligned.m8n8.x4.shared.b16 {%0,%1,%2,%3}, [%4];"
        : "=r"(r[0]), "=r"(r[1]), "=r"(r[2]), "=r"(r[3]) : "r"(addr));
}
__device__ __forceinline__ void mma_bf16(float* c, const uint32_t* a,
                                         uint32_t b0, uint32_t b1) {
    asm volatile("mma.sync.aligned.m16n8k16.row.col.f32.bf16.bf16.f32 "
        "{%0,%1,%2,%3}, {%4,%5,%6,%7}, {%8,%9}, {%0,%1,%2,%3};"
        : "+f"(c[0]), "+f"(c[1]), "+f"(c[2]), "+f"(c[3])
        : "r"(a[0]), "r"(a[1]), "r"(a[2]), "r"(a[3]), "r"(b0), "r"(b1));
}
__device__ __forceinline__ float4 ldcg4(const float4* p) {
    float4 v;
    asm volatile("ld.global.cg.v4.f32 {%0,%1,%2,%3}, [%4];"
        : "=f"(v.x), "=f"(v.y), "=f"(v.z), "=f"(v.w) : "l"(p));
    return v;
}
__device__ __forceinline__ uint4 ldcg4u(const uint4* p) {
    uint4 v;
    asm volatile("ld.global.cg.v4.u32 {%0,%1,%2,%3}, [%4];"
        : "=r"(v.x), "=r"(v.y), "=r"(v.z), "=r"(v.w) : "l"(p));
    return v;
}
__device__ __forceinline__ uint32_t pack_hi2(float a, float b) {
    return (uint32_t)__bfloat16_as_ushort(__float2bfloat16_rn(a)) |
           ((uint32_t)__bfloat16_as_ushort(__float2bfloat16_rn(b)) << 16);
}
__device__ __forceinline__ float bf_res(float x) {
    return x - __bfloat162float(__float2bfloat16_rn(x));
}

// ---------------- pre-kernel: W -> fragment-ordered bf16 hi/lo ----------------
__global__ void wfrag_kernel(const float* __restrict__ W) {
    const int tid = blockIdx.x * blockDim.x + threadIdx.x;   // 8192 threads
    const int ks   = tid >> 9;
    const int jblk = (tid >> 5) & 15;
    const int lane = tid & 31;
    const int n  = jblk * 8 + (lane >> 2);
    const int kk = ks * 16 + (lane & 3) * 2;

    const float w0 = W[(kk + 0) * H_DIM + n];
    const float w1 = W[(kk + 1) * H_DIM + n];
    const float w8 = W[(kk + 8) * H_DIM + n];
    const float w9 = W[(kk + 9) * H_DIM + n];

    uint4 f;
    f.x = pack_hi2(w0, w1);
    f.y = pack_hi2(w8, w9);
    f.z = pack_hi2(bf_res(w0), bf_res(w1));
    f.w = pack_hi2(bf_res(w8), bf_res(w9));
    g_wfrag[tid] = f;
}

// ---------------- producer: gather one tile into buffer ----------------
__device__ __forceinline__ void produce_tile(char* buf, const int* nodes,
                                             const int* neigh, const float4* f4,
                                             int rowBase, int Bn,
                                             int pwid, int lane)
{
    const int rbase = pwid * 8;
    const int b0 = rowBase + rbase;
    int* scN = (int*)(buf + SM_IDX) + pwid * 96;   // [0..7]=nodes, [8..87]=neigh

    if (b0 + 8 <= Bn) {
        if (lane < 2)
            ((int4*)scN)[lane] = ((const int4*)(nodes + b0))[lane];
        if (lane < 20)
            ((int4*)(scN + 8))[lane] = ((const int4*)(neigh + (size_t)b0 * 10))[lane];
    } else if (b0 < Bn) {
        for (int i = lane; i < 8; i += 32) {
            const int b = b0 + i;
            scN[i] = (b < Bn) ? nodes[b] : 0;
        }
        for (int i = lane; i < 80; i += 32) {
            const int b = b0 + i / 10;
            scN[8 + i] = (b < Bn) ? neigh[(size_t)b * 10 + (i % 10)] : 0;
        }
    }
    __syncwarp();

    #pragma unroll
    for (int i = 0; i < 8; ++i) {
        const int b = b0 + i;
        if (b < Bn) {
            const int node = scN[i];
            const int* ni = scN + 8 + i * 10;

            float4 vs = ldcg4(f4 + (size_t)node * 32 + lane);
            float4 v0 = ldcg4(f4 + (size_t)ni[0] * 32 + lane);
            float4 v1 = ldcg4(f4 + (size_t)ni[1] * 32 + lane);
            float4 v2 = ldcg4(f4 + (size_t)ni[2] * 32 + lane);
            float4 v3 = ldcg4(f4 + (size_t)ni[3] * 32 + lane);
            float4 v4 = ldcg4(f4 + (size_t)ni[4] * 32 + lane);
            float4 s;
            s.x = v0.x + v1.x + v2.x + v3.x + v4.x;
            s.y = v0.y + v1.y + v2.y + v3.y + v4.y;
            s.z = v0.z + v1.z + v2.z + v3.z + v4.z;
            s.w = v0.w + v1.w + v2.w + v3.w + v4.w;
            v0 = ldcg4(f4 + (size_t)ni[5] * 32 + lane);
            v1 = ldcg4(f4 + (size_t)ni[6] * 32 + lane);
            v2 = ldcg4(f4 + (size_t)ni[7] * 32 + lane);
            v3 = ldcg4(f4 + (size_t)ni[8] * 32 + lane);
            v4 = ldcg4(f4 + (size_t)ni[9] * 32 + lane);
            s.x += v0.x + v1.x + v2.x + v3.x + v4.x;
            s.y += v0.y + v1.y + v2.y + v3.y + v4.y;
            s.z += v0.z + v1.z + v2.z + v3.z + v4.z;
            s.w += v0.w + v1.w + v2.w + v3.w + v4.w;
            s.x *= 0.1f; s.y *= 0.1f; s.z *= 0.1f; s.w *= 0.1f;

            const int r = rbase + i;
            const uint32_t oS = (uint32_t)r * (A_STRIDE * 2) + lane * 8;  // k = lane*4
            const uint32_t oM = oS + 256;                                 // k = 128+lane*4
            *(uint2*)(buf + oS) = make_uint2(pack_hi2(vs.x, vs.y), pack_hi2(vs.z, vs.w));
            *(uint2*)(buf + SM_ALO + oS) = make_uint2(pack_hi2(bf_res(vs.x), bf_res(vs.y)),
                                                      pack_hi2(bf_res(vs.z), bf_res(vs.w)));
            *(uint2*)(buf + oM) = make_uint2(pack_hi2(s.x, s.y), pack_hi2(s.z, s.w));
            *(uint2*)(buf + SM_ALO + oM) = make_uint2(pack_hi2(bf_res(s.x), bf_res(s.y)),
                                                      pack_hi2(bf_res(s.z), bf_res(s.w)));
        }
    }
}

// ---------------- consumer: MMA + epilogue for one tile ----------------
__device__ __forceinline__ void consume_tile(uint32_t bufb, float* out,
                                             int rowBase, int Bn,
                                             int wid, int lane)
{
    const int n0w = wid * 4;   // col-block base (8-col units)
    const uint4* wbase = &g_wfrag[n0w * 32 + lane];   // + ks*512 + j*32

    float acc0[4][4], acc1[4][4];
    #pragma unroll
    for (int j = 0; j < 4; ++j)
        #pragma unroll
        for (int c = 0; c < 4; ++c) { acc0[j][c] = 0.f; acc1[j][c] = 0.f; }

    const uint32_t aAddr0 = bufb + (uint32_t)(((lane & 15)) * A_STRIDE + (lane >> 4) * 8) * 2;
    const uint32_t aAddr1 = aAddr0 + 16 * A_STRIDE * 2;

    uint4 fA[4], fB[4];
    #pragma unroll
    for (int j = 0; j < 4; ++j) fA[j] = ldcg4u(wbase + 0 * 512 + j * 32);
    #pragma unroll
    for (int j = 0; j < 4; ++j) fB[j] = ldcg4u(wbase + 1 * 512 + j * 32);

    #pragma unroll 4
    for (int ks = 0; ks < 16; ++ks) {
        uint32_t aHi0[4], aLo0[4], aHi1[4], aLo1[4];
        const uint32_t ao = (uint32_t)(ks * 16) * 2;
        ldsm_x4(aHi0, aAddr0 + ao);
        ldsm_x4(aLo0, aAddr0 + SM_ALO + ao);
        ldsm_x4(aHi1, aAddr1 + ao);
        ldsm_x4(aLo1, aAddr1 + SM_ALO + ao);

        uint4* fc = (ks & 1) ? fB : fA;
        #pragma unroll
        for (int j = 0; j < 4; ++j) {
            uint4 f = fc[j];
            mma_bf16(acc0[j], aHi0, f.x, f.y);
            mma_bf16(acc0[j], aHi0, f.z, f.w);
            mma_bf16(acc0[j], aLo0, f.x, f.y);
            mma_bf16(acc1[j], aHi1, f.x, f.y);
            mma_bf16(acc1[j], aHi1, f.z, f.w);
            mma_bf16(acc1[j], aLo1, f.x, f.y);
        }
        const int kn = (ks + 2) & 15;
        #pragma unroll
        for (int j = 0; j < 4; ++j) fc[j] = ldcg4u(wbase + kn * 512 + j * 32);
    }

    #pragma unroll
    for (int h = 0; h < 2; ++h) {
        float (*acc)[4] = h ? acc1 : acc0;
        const int r0 = rowBase + h * 16 + (lane >> 2);
        const int r1 = r0 + 8;
        const int c0 = wid * 32 + (lane & 3) * 2;
        #pragma unroll
        for (int j = 0; j < 4; ++j) {
            const int col = c0 + j * 8;
            if (r0 < Bn) {
                float2 o;
                o.x = fmaxf(acc[j][0], 0.f);
                o.y = fmaxf(acc[j][1], 0.f);
                *(float2*)&out[(size_t)r0 * H_DIM + col] = o;
            }
            if (r1 < Bn) {
                float2 o;
                o.x = fmaxf(acc[j][2], 0.f);
                o.y = fmaxf(acc[j][3], 0.f);
                *(float2*)&out[(size_t)r1 * H_DIM + col] = o;
            }
        }
    }
}

// ---------------- main kernel: persistent, warp-specialized ----------------
__global__ __launch_bounds__(NTHREADS, 2)
void sage_main_kernel(const int* __restrict__ nodes,
                      const int* __restrict__ neigh,
                      const float* __restrict__ feat,
                      float* __restrict__ out,
                      int Bn, int nTiles)
{
    extern __shared__ char sm[];
    const uint32_t smb = s2u(sm);
    const int t = threadIdx.x;
    const int wid = t >> 5;          // 0..7
    const int lane = t & 31;
    const float4* f4 = (const float4*)feat;

    const int G = gridDim.x;
    // number of tiles this CTA owns
    int nSteps = 0;
    if ((int)blockIdx.x < nTiles)
        nSteps = (nTiles - blockIdx.x + G - 1) / G;

    for (int s = 0; s <= nSteps; ++s) {
        if (wid >= 4) {
            // producers: fill buffer s&1 with tile(s)
            if (s < nSteps) {
                const int tile = blockIdx.x + s * G;
                produce_tile(sm + (s & 1) * BUF_BYTES, nodes, neigh, f4,
                             tile * TILE_M, Bn, wid - 4, lane);
            }
        } else {
            // consumers: eat buffer (s-1)&1 with tile(s-1)
            if (s > 0) {
                const int tile = blockIdx.x + (s - 1) * G;
                consume_tile(smb + ((s - 1) & 1) * BUF_BYTES, out,
                             tile * TILE_M, Bn, wid, lane);
            }
        }
        __syncthreads();
    }
}

extern "C" void kernel_launch(void* const* d_in, const int* in_sizes, int n_in,
                              void* d_out, int out_size)
{
    const int*   nodes  = (const int*)d_in[0];
    const int*   neigh  = (const int*)d_in[1];
    const float* feat   = (const float*)d_in[2];
    const float* weight = (const float*)d_in[3];
    float*       out    = (float*)d_out;
    const int Bn = in_sizes[0];
    const int nTiles = (Bn + TILE_M - 1) / TILE_M;

    wfrag_kernel<<<64, 128>>>(weight);

    cudaFuncSetAttribute(sage_main_kernel,
                         cudaFuncAttributeMaxDynamicSharedMemorySize, SM_TOTAL);

    int grid = 296;                 // 2 CTAs/SM x 148 SMs
    if (grid > nTiles) grid = nTiles;
    sage_main_kernel<<<grid, NTHREADS, SM_TOTAL>>>(nodes, neigh, feat, out, Bn, nTiles);
}

// round 15
// speedup vs baseline: 1.4697x; 1.4697x over previous
#include <cuda_runtime.h>
#include <cuda_fp16.h>
#include <cstdint>

// GraphSage: out = relu( [self | mean(neigh)] @ W ),  B=50000, D=128, H=128, K=256.
// Round-14: single-product fp16 HMMA (m16n8k16.f32.f16.f16.f32).
// fp16 mantissa (11 bits) -> output norm rel err ~2-4e-4, under the 1e-3
// threshold with margin (single bf16 would fail; bf16x3 was 4.6e-6 overkill).
// vs round-11 best: 3x fewer MMAs, half the LDSM/W-frag/A-smem traffic.
// Structure otherwise identical to round-11 (paired-row gather, W prefetch
// depth 2, m32n32 warp tiles, 4 CTAs/SM, one barrier).

#define NTHREADS 128
#define TILE_M   32
#define H_DIM    128
#define A_STRIDE 264            // elements; 528B rows = 33 chunks, ldmatrix conflict-free

#define SM_IDX   (TILE_M * A_STRIDE * 2)            // 16896 (A tile, fp16 hi only)
#define SM_TOTAL (SM_IDX + 4 * 96 * 4)              // 18432 B (static)

// W fragments: [kstep 0..15][colblk 0..15][lane 0..31] -> uint2{b0,b1} fp16x2
__device__ uint2 g_wfrag[16 * 16 * 32];

__device__ __forceinline__ uint32_t s2u(const void* p) {
    uint32_t a;
    asm("{ .reg .u64 t; cvta.to.shared.u64 t, %1; cvt.u32.u64 %0, t; }" : "=r"(a) : "l"(p));
    return a;
}
__device__ __forceinline__ void ldsm_x4(uint32_t* r, uint32_t addr) {
    asm volatile("ldmatrix.sync.aligned.m8n8.x4.shared.b16 {%0,%1,%2,%3}, [%4];"
        : "=r"(r[0]), "=r"(r[1]), "=r"(r[2]), "=r"(r[3]) : "r"(addr));
}
__device__ __forceinline__ void mma_fp16(float* c, const uint32_t* a,
                                         uint32_t b0, uint32_t b1) {
    asm volatile("mma.sync.aligned.m16n8k16.row.col.f32.f16.f16.f32 "
        "{%0,%1,%2,%3}, {%4,%5,%6,%7}, {%8,%9}, {%0,%1,%2,%3};"
        : "+f"(c[0]), "+f"(c[1]), "+f"(c[2]), "+f"(c[3])
        : "r"(a[0]), "r"(a[1]), "r"(a[2]), "r"(a[3]), "r"(b0), "r"(b1));
}
__device__ __forceinline__ float4 ldcg4(const float4* p) {
    float4 v;
    asm volatile("ld.global.cg.v4.f32 {%0,%1,%2,%3}, [%4];"
        : "=f"(v.x), "=f"(v.y), "=f"(v.z), "=f"(v.w) : "l"(p));
    return v;
}
__device__ __forceinline__ uint2 ldcg2u(const uint2* p) {
    uint2 v;
    asm volatile("ld.global.cg.v2.u32 {%0,%1}, [%2];"
        : "=r"(v.x), "=r"(v.y) : "l"(p));
    return v;
}
__device__ __forceinline__ uint32_t ph2(float a, float b) {
    __half2 h = __floats2half2_rn(a, b);
    return *(uint32_t*)&h;
}

// ---------------- pre-kernel: W -> fragment-ordered fp16 ----------------
// mma m16n8k16 B (col-major k16n8) lane layout:
//   b0 = {W[k0][n], W[k0+1][n]},  b1 = {W[k0+8][n], W[k0+9][n]}
//   with n = lane/4, k0 = (lane%4)*2
__global__ void wfrag_kernel(const float* __restrict__ W) {
    const int tid = blockIdx.x * blockDim.x + threadIdx.x;   // 8192 threads
    const int ks   = tid >> 9;
    const int jblk = (tid >> 5) & 15;
    const int lane = tid & 31;
    const int n  = jblk * 8 + (lane >> 2);
    const int kk = ks * 16 + (lane & 3) * 2;

    uint2 f;
    f.x = ph2(W[(kk + 0) * H_DIM + n], W[(kk + 1) * H_DIM + n]);
    f.y = ph2(W[(kk + 8) * H_DIM + n], W[(kk + 9) * H_DIM + n]);
    g_wfrag[tid] = f;
}

// store one gathered row (self vs, mean s) into A smem (fp16)
__device__ __forceinline__ void store_row(char* sm, int r, int lane,
                                          float4 vs, float4 s) {
    const uint32_t oS = (uint32_t)r * (A_STRIDE * 2) + lane * 8;  // k = lane*4
    const uint32_t oM = oS + 256;                                 // k = 128+lane*4
    *(uint2*)(sm + oS) = make_uint2(ph2(vs.x, vs.y), ph2(vs.z, vs.w));
    *(uint2*)(sm + oM) = make_uint2(ph2(s.x, s.y), ph2(s.z, s.w));
}

// ---------------- main kernel ----------------
__global__ __launch_bounds__(NTHREADS, 4)
void sage_main_kernel(const int* __restrict__ nodes,
                      const int* __restrict__ neigh,
                      const float* __restrict__ feat,
                      float* __restrict__ out,
                      int Bn)
{
    __shared__ char sm[SM_TOTAL];
    const uint32_t smb = s2u(sm);
    const int t = threadIdx.x;
    const int wid = t >> 5;          // 0..3
    const int lane = t & 31;
    const int rowBase = blockIdx.x * TILE_M;

    const float4* f4 = (const float4*)feat;

    // ---------- index prefetch: warp covers rows wid*8 .. wid*8+7 ----------
    const int rbase = wid * 8;
    const int b0 = rowBase + rbase;
    int* scN = (int*)(sm + SM_IDX) + wid * 96;   // [0..7]=nodes, [8..87]=neigh

    if (b0 + 8 <= Bn) {
        if (lane < 2)
            ((int4*)scN)[lane] = ((const int4*)(nodes + b0))[lane];
        if (lane < 20)
            ((int4*)(scN + 8))[lane] = ((const int4*)(neigh + (size_t)b0 * 10))[lane];
    } else if (b0 < Bn) {
        for (int i = lane; i < 8; i += 32) {
            const int b = b0 + i;
            scN[i] = (b < Bn) ? nodes[b] : 0;
        }
        for (int i = lane; i < 80; i += 32) {
            const int b = b0 + i / 10;
            scN[8 + i] = (b < Bn) ? neigh[(size_t)b * 10 + (i % 10)] : 0;
        }
    }
    __syncwarp();

    // ---------- gather: paired rows, interleaved batches (12 + 10 loads) ----------
    #pragma unroll
    for (int ip = 0; ip < 4; ++ip) {
        const int i0 = ip * 2, i1 = i0 + 1;
        const int bA = b0 + i0, bB = b0 + i1;

        if (bB < Bn) {
            const int* nA = scN + 8 + i0 * 10;
            const int* nB = scN + 8 + i1 * 10;

            // batch 1: 2 selves + 5+5 neighbors = 12 loads in flight
            float4 vsA = ldcg4(f4 + (size_t)scN[i0] * 32 + lane);
            float4 vsB = ldcg4(f4 + (size_t)scN[i1] * 32 + lane);
            float4 a0 = ldcg4(f4 + (size_t)nA[0] * 32 + lane);
            float4 a1 = ldcg4(f4 + (size_t)nA[1] * 32 + lane);
            float4 a2 = ldcg4(f4 + (size_t)nA[2] * 32 + lane);
            float4 a3 = ldcg4(f4 + (size_t)nA[3] * 32 + lane);
            float4 a4 = ldcg4(f4 + (size_t)nA[4] * 32 + lane);
            float4 c0 = ldcg4(f4 + (size_t)nB[0] * 32 + lane);
            float4 c1 = ldcg4(f4 + (size_t)nB[1] * 32 + lane);
            float4 c2 = ldcg4(f4 + (size_t)nB[2] * 32 + lane);
            float4 c3 = ldcg4(f4 + (size_t)nB[3] * 32 + lane);
            float4 c4 = ldcg4(f4 + (size_t)nB[4] * 32 + lane);

            float4 sA, sB;
            sA.x = a0.x + a1.x + a2.x + a3.x + a4.x;
            sA.y = a0.y + a1.y + a2.y + a3.y + a4.y;
            sA.z = a0.z + a1.z + a2.z + a3.z + a4.z;
            sA.w = a0.w + a1.w + a2.w + a3.w + a4.w;
            sB.x = c0.x + c1.x + c2.x + c3.x + c4.x;
            sB.y = c0.y + c1.y + c2.y + c3.y + c4.y;
            sB.z = c0.z + c1.z + c2.z + c3.z + c4.z;
            sB.w = c0.w + c1.w + c2.w + c3.w + c4.w;

            // batch 2: 5+5 neighbors
            a0 = ldcg4(f4 + (size_t)nA[5] * 32 + lane);
            a1 = ldcg4(f4 + (size_t)nA[6] * 32 + lane);
            a2 = ldcg4(f4 + (size_t)nA[7] * 32 + lane);
            a3 = ldcg4(f4 + (size_t)nA[8] * 32 + lane);
            a4 = ldcg4(f4 + (size_t)nA[9] * 32 + lane);
            c0 = ldcg4(f4 + (size_t)nB[5] * 32 + lane);
            c1 = ldcg4(f4 + (size_t)nB[6] * 32 + lane);
            c2 = ldcg4(f4 + (size_t)nB[7] * 32 + lane);
            c3 = ldcg4(f4 + (size_t)nB[8] * 32 + lane);
            c4 = ldcg4(f4 + (size_t)nB[9] * 32 + lane);

            sA.x += a0.x + a1.x + a2.x + a3.x + a4.x;
            sA.y += a0.y + a1.y + a2.y + a3.y + a4.y;
            sA.z += a0.z + a1.z + a2.z + a3.z + a4.z;
            sA.w += a0.w + a1.w + a2.w + a3.w + a4.w;
            sB.x += c0.x + c1.x + c2.x + c3.x + c4.x;
            sB.y += c0.y + c1.y + c2.y + c3.y + c4.y;
            sB.z += c0.z + c1.z + c2.z + c3.z + c4.z;
            sB.w += c0.w + c1.w + c2.w + c3.w + c4.w;

            sA.x *= 0.1f; sA.y *= 0.1f; sA.z *= 0.1f; sA.w *= 0.1f;
            sB.x *= 0.1f; sB.y *= 0.1f; sB.z *= 0.1f; sB.w *= 0.1f;

            store_row(sm, rbase + i0, lane, vsA, sA);
            store_row(sm, rbase + i1, lane, vsB, sB);
        } else if (bA < Bn) {
            const int* nA = scN + 8 + i0 * 10;
            float4 vsA = ldcg4(f4 + (size_t)scN[i0] * 32 + lane);
            float4 s = make_float4(0.f, 0.f, 0.f, 0.f);
            #pragma unroll
            for (int ns = 0; ns < 10; ++ns) {
                float4 v = ldcg4(f4 + (size_t)nA[ns] * 32 + lane);
                s.x += v.x; s.y += v.y; s.z += v.z; s.w += v.w;
            }
            s.x *= 0.1f; s.y *= 0.1f; s.z *= 0.1f; s.w *= 0.1f;
            store_row(sm, rbase + i0, lane, vsA, s);
        }
    }
    __syncthreads();   // the only CTA barrier

    // ---------- MMA: warp tile m32 x n32, 16 k-steps, W prefetch depth 2 ----------
    const int n0w = wid * 4;   // col-block base (8-col units)
    const uint2* wbase = &g_wfrag[n0w * 32 + lane];   // + ks*512 + j*32

    float acc0[4][4], acc1[4][4];
    #pragma unroll
    for (int j = 0; j < 4; ++j)
        #pragma unroll
        for (int c = 0; c < 4; ++c) { acc0[j][c] = 0.f; acc1[j][c] = 0.f; }

    const uint32_t aAddr0 = smb + (uint32_t)(((lane & 15)) * A_STRIDE + (lane >> 4) * 8) * 2;
    const uint32_t aAddr1 = aAddr0 + 16 * A_STRIDE * 2;

    uint2 fA[4], fB[4];
    #pragma unroll
    for (int j = 0; j < 4; ++j) fA[j] = ldcg2u(wbase + 0 * 512 + j * 32);
    #pragma unroll
    for (int j = 0; j < 4; ++j) fB[j] = ldcg2u(wbase + 1 * 512 + j * 32);

    #pragma unroll 4
    for (int ks = 0; ks < 16; ++ks) {
        uint32_t a0[4], a1[4];
        const uint32_t ao = (uint32_t)(ks * 16) * 2;
        ldsm_x4(a0, aAddr0 + ao);
        ldsm_x4(a1, aAddr1 + ao);

        uint2* fc = (ks & 1) ? fB : fA;
        #pragma unroll
        for (int j = 0; j < 4; ++j) {
            uint2 f = fc[j];
            mma_fp16(acc0[j], a0, f.x, f.y);
            mma_fp16(acc1[j], a1, f.x, f.y);
        }
        const int kn = (ks + 2) & 15;
        #pragma unroll
        for (int j = 0; j < 4; ++j) fc[j] = ldcg2u(wbase + kn * 512 + j * 32);
    }

    // ---------- epilogue: relu + float2 stores ----------
    #pragma unroll
    for (int h = 0; h < 2; ++h) {
        float (*acc)[4] = h ? acc1 : acc0;
        const int r0 = rowBase + h * 16 + (lane >> 2);
        const int r1 = r0 + 8;
        const int c0 = wid * 32 + (lane & 3) * 2;
        #pragma unroll
        for (int j = 0; j < 4; ++j) {
            const int col = c0 + j * 8;
            if (r0 < Bn) {
                float2 o;
                o.x = fmaxf(acc[j][0], 0.f);
                o.y = fmaxf(acc[j][1], 0.f);
                *(float2*)&out[(size_t)r0 * H_DIM + col] = o;
            }
            if (r1 < Bn) {
                float2 o;
                o.x = fmaxf(acc[j][2], 0.f);
                o.y = fmaxf(acc[j][3], 0.f);
                *(float2*)&out[(size_t)r1 * H_DIM + col] = o;
            }
        }
    }
}

extern "C" void kernel_launch(void* const* d_in, const int* in_sizes, int n_in,
                              void* d_out, int out_size)
{
    const int*   nodes  = (const int*)d_in[0];
    const int*   neigh  = (const int*)d_in[1];
    const float* feat   = (const float*)d_in[2];
    const float* weight = (const float*)d_in[3];
    float*       out    = (float*)d_out;
    const int Bn = in_sizes[0];

    wfrag_kernel<<<64, 128>>>(weight);

    const int grid = (Bn + TILE_M - 1) / TILE_M;
    sage_main_kernel<<<grid, NTHREADS>>>(nodes, neigh, feat, out, Bn);
}